// round 2
// baseline (speedup 1.0000x reference)
#include <cuda_runtime.h>
#include <cuda_bf16.h>
#include <math.h>

// Problem constants
#define NN   3072
#define HH   8
#define DH   32
#define HID  256
#define DEG  16
#define EE   (NN*DEG)      // 49152
#define EDIM 32
#define FFN  1024

// ---------------------------------------------------------------------------
// Scratch (no allocations allowed -> __device__ globals)
// ---------------------------------------------------------------------------
__device__ float g_Q[NN*HID];
__device__ float g_K[NN*HID];
__device__ float g_V[NN*HID];
__device__ float g_eatt[EE*HH];
__device__ float g_attn[NN*HID];
__device__ float g_t1[NN*HID];
__device__ float g_x1[NN*HID];
__device__ float g_f[NN*FFN];
__device__ float g_t2[NN*HID];

// ---------------------------------------------------------------------------
// Generic fp32 tiled GEMM: C[M,Nc] = A[M,K] @ B[K,Nc] + bias (+ optional ReLU)
// BM=64, BN=64, BK=16, 256 threads, 4x4 microtile per thread.
// Sizes here are always multiples of the tiles -> no bounds checks.
// ---------------------------------------------------------------------------
#define BM 64
#define BN 64
#define BK 16
#define TM 4
#define TN 4

__global__ void __launch_bounds__(256) gemm_kernel(
    const float* __restrict__ A, const float* __restrict__ B,
    const float* __restrict__ bias, float* __restrict__ C,
    int M, int Nc, int K, int relu)
{
    __shared__ float As[BM][BK+1];
    __shared__ float Bs[BK][BN];

    const int tid = threadIdx.x;
    const int tx  = tid & 15;          // 0..15 -> column group
    const int ty  = tid >> 4;          // 0..15 -> row group

    const int bx = blockIdx.x;
    const int by = blockIdx.y;

    const float* Ab = A + (size_t)by * BM * K;
    const float* Bb = B + (size_t)bx * BN;

    // load mapping
    const int arow  = tid >> 2;        // 64 rows, 4 float4 per row
    const int acol4 = tid & 3;
    const int brow  = tid >> 4;        // 16 rows, 16 float4 per row
    const int bcol4 = tid & 15;

    float acc[TM][TN];
#pragma unroll
    for (int i = 0; i < TM; i++)
#pragma unroll
        for (int j = 0; j < TN; j++) acc[i][j] = 0.f;

    for (int k0 = 0; k0 < K; k0 += BK) {
        float4 av = *(const float4*)(Ab + (size_t)arow * K + k0 + acol4 * 4);
        As[arow][acol4*4+0] = av.x;
        As[arow][acol4*4+1] = av.y;
        As[arow][acol4*4+2] = av.z;
        As[arow][acol4*4+3] = av.w;
        float4 bv = *(const float4*)(Bb + (size_t)(k0 + brow) * Nc + bcol4 * 4);
        *(float4*)&Bs[brow][bcol4*4] = bv;
        __syncthreads();

#pragma unroll
        for (int kk = 0; kk < BK; kk++) {
            float a[TM], b[TN];
#pragma unroll
            for (int i = 0; i < TM; i++) a[i] = As[ty*TM+i][kk];
#pragma unroll
            for (int j = 0; j < TN; j++) b[j] = Bs[kk][tx*TN+j];
#pragma unroll
            for (int i = 0; i < TM; i++)
#pragma unroll
                for (int j = 0; j < TN; j++)
                    acc[i][j] = fmaf(a[i], b[j], acc[i][j]);
        }
        __syncthreads();
    }

#pragma unroll
    for (int i = 0; i < TM; i++) {
        int row = by * BM + ty * TM + i;
#pragma unroll
        for (int j = 0; j < TN; j++) {
            int col = bx * BN + tx * TN + j;
            float v = acc[i][j] + bias[col];
            if (relu) v = fmaxf(v, 0.f);
            C[(size_t)row * Nc + col] = v;
        }
    }
}

// ---------------------------------------------------------------------------
// Edge attention bias: eatt[e,h] = edge_features[e,:] @ We[:,h] + be[h]
// ---------------------------------------------------------------------------
__global__ void edge_kernel(const float* __restrict__ ef,
                            const float* __restrict__ We,
                            const float* __restrict__ be,
                            float* __restrict__ eatt)
{
    __shared__ float sWe[EDIM*HH];   // 256 floats
    __shared__ float sbe[HH];
    if (threadIdx.x < EDIM*HH) sWe[threadIdx.x] = We[threadIdx.x];
    if (threadIdx.x < HH)      sbe[threadIdx.x] = be[threadIdx.x];
    __syncthreads();

    int e = blockIdx.x * blockDim.x + threadIdx.x;
    if (e >= EE) return;

    float acc[HH];
#pragma unroll
    for (int h = 0; h < HH; h++) acc[h] = sbe[h];

    const float* row = ef + (size_t)e * EDIM;
#pragma unroll
    for (int k = 0; k < EDIM; k++) {
        float x = row[k];
#pragma unroll
        for (int h = 0; h < HH; h++) acc[h] = fmaf(x, sWe[k*HH+h], acc[h]);
    }
#pragma unroll
    for (int h = 0; h < HH; h++) eatt[(size_t)e*HH + h] = acc[h];
}

// ---------------------------------------------------------------------------
// Sparse attention: one block per node, one warp per head.
// Dedup rule: among duplicate neighbors, keep the LAST occurrence
// (matches sequential XLA scatter "last write wins" for edge bias, and the
// fact that a duplicated (n,m) is a single softmax column in the reference).
// ---------------------------------------------------------------------------
__global__ void __launch_bounds__(HH*32) attn_kernel(
    const float* __restrict__ Q, const float* __restrict__ K,
    const float* __restrict__ V, const int* __restrict__ nbr,
    const float* __restrict__ eatt, float* __restrict__ out)
{
    const int n = blockIdx.x;
    __shared__ int snb[DEG];
    __shared__ int skeep[DEG];

    const int tid = threadIdx.x;
    if (tid < DEG) snb[tid] = nbr[n*DEG + tid];
    __syncthreads();
    if (tid < DEG) {
        int keep = 1;
        int m = snb[tid];
        for (int j = tid + 1; j < DEG; j++)
            if (snb[j] == m) keep = 0;
        skeep[tid] = keep;
    }
    __syncthreads();

    const int h    = tid >> 5;
    const int lane = tid & 31;
    const unsigned FULL = 0xffffffffu;

    const float q = Q[(size_t)n*HID + h*DH + lane];

    float sc = -1e30f;   // lane j<DEG holds score_j; others -inf
#pragma unroll
    for (int j = 0; j < DEG; j++) {
        if (skeep[j]) {
            float v = q * K[(size_t)snb[j]*HID + h*DH + lane];
#pragma unroll
            for (int o = 16; o > 0; o >>= 1)
                v += __shfl_xor_sync(FULL, v, o);
            v = v * 0.17677669529663687f + eatt[(size_t)(n*DEG + j)*HH + h];
            if (lane == j) sc = v;
        }
    }

    // softmax over the 32 lanes (inactive lanes carry -1e30 -> p=0)
    float m = sc;
#pragma unroll
    for (int o = 16; o > 0; o >>= 1)
        m = fmaxf(m, __shfl_xor_sync(FULL, m, o));
    float p = (sc > -1e29f) ? __expf(sc - m) : 0.f;
    float s = p;
#pragma unroll
    for (int o = 16; o > 0; o >>= 1)
        s += __shfl_xor_sync(FULL, s, o);
    p /= s;

    float acc = 0.f;
#pragma unroll
    for (int j = 0; j < DEG; j++) {
        if (skeep[j]) {
            float pj = __shfl_sync(FULL, p, j);
            acc = fmaf(pj, V[(size_t)snb[j]*HID + h*DH + lane], acc);
        }
    }
    out[(size_t)n*HID + h*DH + lane] = acc;
}

// ---------------------------------------------------------------------------
// Fused residual add + LayerNorm over HID=256. One block (256 thr) per row.
// ---------------------------------------------------------------------------
__global__ void __launch_bounds__(HID) add_ln_kernel(
    const float* __restrict__ a, const float* __restrict__ res,
    const float* __restrict__ g, const float* __restrict__ b,
    float* __restrict__ out)
{
    __shared__ float red[8];
    const int row = blockIdx.x;
    const int tid = threadIdx.x;
    const int lane = tid & 31, w = tid >> 5;
    const unsigned FULL = 0xffffffffu;

    float x = a[(size_t)row*HID + tid] + res[(size_t)row*HID + tid];

    // mean
    float v = x;
#pragma unroll
    for (int o = 16; o > 0; o >>= 1) v += __shfl_xor_sync(FULL, v, o);
    if (lane == 0) red[w] = v;
    __syncthreads();
    float t = (tid < 8) ? red[tid] : 0.f;
    if (w == 0) {
#pragma unroll
        for (int o = 4; o > 0; o >>= 1) t += __shfl_xor_sync(FULL, t, o);
        if (lane == 0) red[0] = t;
    }
    __syncthreads();
    float mu = red[0] * (1.f / HID);
    __syncthreads();

    // variance
    float d = x - mu;
    v = d * d;
#pragma unroll
    for (int o = 16; o > 0; o >>= 1) v += __shfl_xor_sync(FULL, v, o);
    if (lane == 0) red[w] = v;
    __syncthreads();
    t = (tid < 8) ? red[tid] : 0.f;
    if (w == 0) {
#pragma unroll
        for (int o = 4; o > 0; o >>= 1) t += __shfl_xor_sync(FULL, t, o);
        if (lane == 0) red[0] = t;
    }
    __syncthreads();
    float var = red[0] * (1.f / HID);

    out[(size_t)row*HID + tid] = d * rsqrtf(var + 1e-5f) * g[tid] + b[tid];
}

// ---------------------------------------------------------------------------
// Launch
// ---------------------------------------------------------------------------
extern "C" void kernel_launch(void* const* d_in, const int* in_sizes, int n_in,
                              void* d_out, int out_size)
{
    const float* node = (const float*)d_in[0];
    const int*   nbr  = (const int*)  d_in[1];
    const float* ef   = (const float*)d_in[2];
    const float* Wq   = (const float*)d_in[3];
    const float* bq   = (const float*)d_in[4];
    const float* Wk   = (const float*)d_in[5];
    const float* bk   = (const float*)d_in[6];
    const float* Wv   = (const float*)d_in[7];
    const float* bv   = (const float*)d_in[8];
    const float* We   = (const float*)d_in[9];
    const float* be   = (const float*)d_in[10];
    const float* Wo   = (const float*)d_in[11];
    const float* bo   = (const float*)d_in[12];
    const float* ln1g = (const float*)d_in[13];
    const float* ln1b = (const float*)d_in[14];
    const float* ln2g = (const float*)d_in[15];
    const float* ln2b = (const float*)d_in[16];
    const float* Wf1  = (const float*)d_in[17];
    const float* bf1  = (const float*)d_in[18];
    const float* Wf2  = (const float*)d_in[19];
    const float* bf2  = (const float*)d_in[20];
    float* out = (float*)d_out;

    // Resolve scratch symbol addresses once (host-side statics; deterministic).
    static float *Qd = nullptr, *Kd, *Vd, *eattd, *attnd, *t1d, *x1d, *fd, *t2d;
    if (!Qd) {
        cudaGetSymbolAddress((void**)&Qd,    g_Q);
        cudaGetSymbolAddress((void**)&Kd,    g_K);
        cudaGetSymbolAddress((void**)&Vd,    g_V);
        cudaGetSymbolAddress((void**)&eattd, g_eatt);
        cudaGetSymbolAddress((void**)&attnd, g_attn);
        cudaGetSymbolAddress((void**)&t1d,   g_t1);
        cudaGetSymbolAddress((void**)&x1d,   g_x1);
        cudaGetSymbolAddress((void**)&fd,    g_f);
        cudaGetSymbolAddress((void**)&t2d,   g_t2);
    }

    dim3 gHID(HID/BN, NN/BM);   // 4 x 48
    dim3 gFFN(FFN/BN, NN/BM);   // 16 x 48

    // QKV projections
    gemm_kernel<<<gHID, 256>>>(node, Wq, bq, Qd, NN, HID, HID, 0);
    gemm_kernel<<<gHID, 256>>>(node, Wk, bk, Kd, NN, HID, HID, 0);
    gemm_kernel<<<gHID, 256>>>(node, Wv, bv, Vd, NN, HID, HID, 0);

    // Edge bias
    edge_kernel<<<(EE + 255)/256, 256>>>(ef, We, be, eattd);

    // Sparse attention
    attn_kernel<<<NN, HH*32>>>(Qd, Kd, Vd, nbr, eattd, attnd);

    // Output projection + residual + LN1
    gemm_kernel<<<gHID, 256>>>(attnd, Wo, bo, t1d, NN, HID, HID, 0);
    add_ln_kernel<<<NN, HID>>>(t1d, node, ln1g, ln1b, x1d);

    // FFN
    gemm_kernel<<<gFFN, 256>>>(x1d, Wf1, bf1, fd, NN, FFN, HID, 1);
    gemm_kernel<<<gHID, 256>>>(fd, Wf2, bf2, t2d, NN, HID, FFN, 0);
    add_ln_kernel<<<NN, HID>>>(t2d, x1d, ln2g, ln2b, out);
}

// round 3
// speedup vs baseline: 1.0186x; 1.0186x over previous
#include <cuda_runtime.h>
#include <cuda_bf16.h>
#include <math.h>
#include <stdint.h>

// Problem constants
#define NN   3072
#define HH   8
#define DH   32
#define HID  256
#define DEG  16
#define EE   (NN*DEG)      // 49152
#define EDIM 32
#define FFN  1024

// ---------------------------------------------------------------------------
// Scratch (no allocations allowed -> __device__ globals)
// ---------------------------------------------------------------------------
__device__ float g_Q[NN*HID];
__device__ float g_K[NN*HID];
__device__ float g_V[NN*HID];
__device__ float g_eatt[EE*HH];
__device__ float g_attn[NN*HID];
__device__ float g_t1[NN*HID];
__device__ float g_x1[NN*HID];
__device__ float g_f[NN*FFN];
__device__ float g_t2[NN*HID];

// ---------------------------------------------------------------------------
// Split-TF32 GEMM via mma.sync.m16n8k8 (fp32-accurate: hi*hi + hi*lo + lo*hi)
// Block tile 128x64, BK=16, 128 threads (4 warps), warp tile 64x32.
// Smem stores (hi,lo) pairs interleaved -> each fragment element is 1 LDS.64.
// ---------------------------------------------------------------------------
#define GBM 128
#define GBN 64
#define GBK 16
#define ASTRIDE (2*GBM + 8)   // 264 words, mod 32 == 8 -> conflict-free pattern
#define BSTRIDE (2*GBN + 8)   // 136 words, mod 32 == 8

__device__ __forceinline__ float trunc13(float x) {
    return __uint_as_float(__float_as_uint(x) & 0xFFFFE000u);
}

__device__ __forceinline__ void mma8(float* c, const uint32_t* a, const uint32_t* b) {
    asm volatile(
        "mma.sync.aligned.m16n8k8.row.col.f32.tf32.tf32.f32 "
        "{%0,%1,%2,%3}, {%4,%5,%6,%7}, {%8,%9}, {%0,%1,%2,%3};\n"
        : "+f"(c[0]), "+f"(c[1]), "+f"(c[2]), "+f"(c[3])
        : "r"(a[0]), "r"(a[1]), "r"(a[2]), "r"(a[3]), "r"(b[0]), "r"(b[1]));
}

template<bool RELU>
__device__ __forceinline__ void gemm_tf32_core(
    const float* __restrict__ A, const float* __restrict__ B,
    const float* __restrict__ bias, float* __restrict__ C,
    int Nc, int K, int bm, int bn)
{
    __shared__ float As[GBK][ASTRIDE];
    __shared__ float Bs[GBK][BSTRIDE];

    const int tid  = threadIdx.x;
    const int lane = tid & 31;
    const int warp = tid >> 5;
    const int wm   = (warp & 1) * 64;   // warp row base within block tile
    const int wn   = (warp >> 1) * 32;  // warp col base
    const int grp  = lane >> 2;
    const int tig  = lane & 3;

    float acc[4][4][4];
#pragma unroll
    for (int i = 0; i < 4; i++)
#pragma unroll
        for (int j = 0; j < 4; j++)
#pragma unroll
            for (int r = 0; r < 4; r++) acc[i][j][r] = 0.f;

#pragma unroll 1
    for (int k0 = 0; k0 < K; k0 += GBK) {
        // ---- load A tile: 128 rows x 16 k. 1 row per thread, 4 float4.
        {
            const int row = tid;
            const float* Ap = A + (size_t)(bm + row) * K + k0;
#pragma unroll
            for (int q = 0; q < 4; q++) {
                float4 v = *(const float4*)(Ap + q * 4);
                float h, l;
                h = trunc13(v.x); l = v.x - h; *(float2*)&As[q*4+0][2*row] = make_float2(h, l);
                h = trunc13(v.y); l = v.y - h; *(float2*)&As[q*4+1][2*row] = make_float2(h, l);
                h = trunc13(v.z); l = v.z - h; *(float2*)&As[q*4+2][2*row] = make_float2(h, l);
                h = trunc13(v.w); l = v.w - h; *(float2*)&As[q*4+3][2*row] = make_float2(h, l);
            }
        }
        // ---- load B tile: 16 k x 64 n. 256 float4 total, 2 per thread.
#pragma unroll
        for (int it = 0; it < 2; it++) {
            const int idx = tid + it * 128;
            const int row = idx >> 4;          // 0..15
            const int c4  = idx & 15;          // 0..15
            float4 v = *(const float4*)(B + (size_t)(k0 + row) * Nc + bn + c4 * 4);
            float h, l;
            h = trunc13(v.x); l = v.x - h; *(float2*)&Bs[row][2*(c4*4+0)] = make_float2(h, l);
            h = trunc13(v.y); l = v.y - h; *(float2*)&Bs[row][2*(c4*4+1)] = make_float2(h, l);
            h = trunc13(v.z); l = v.z - h; *(float2*)&Bs[row][2*(c4*4+2)] = make_float2(h, l);
            h = trunc13(v.w); l = v.w - h; *(float2*)&Bs[row][2*(c4*4+3)] = make_float2(h, l);
        }
        __syncthreads();

        // ---- compute: 2 k-steps of m16n8k8, 3 mma per (mi,ni) for split-tf32
#pragma unroll
        for (int ks = 0; ks < GBK; ks += 8) {
            uint32_t ah[4][4], al[4][4], bh[4][2], bl[4][2];
#pragma unroll
            for (int mi = 0; mi < 4; mi++) {
                const int r = wm + mi * 16 + grp;
                float2 p0 = *(float2*)&As[ks + tig    ][2*r];
                float2 p1 = *(float2*)&As[ks + tig    ][2*(r+8)];
                float2 p2 = *(float2*)&As[ks + tig + 4][2*r];
                float2 p3 = *(float2*)&As[ks + tig + 4][2*(r+8)];
                ah[mi][0] = __float_as_uint(p0.x); al[mi][0] = __float_as_uint(p0.y);
                ah[mi][1] = __float_as_uint(p1.x); al[mi][1] = __float_as_uint(p1.y);
                ah[mi][2] = __float_as_uint(p2.x); al[mi][2] = __float_as_uint(p2.y);
                ah[mi][3] = __float_as_uint(p3.x); al[mi][3] = __float_as_uint(p3.y);
            }
#pragma unroll
            for (int ni = 0; ni < 4; ni++) {
                const int n = wn + ni * 8 + grp;
                float2 q0 = *(float2*)&Bs[ks + tig    ][2*n];
                float2 q1 = *(float2*)&Bs[ks + tig + 4][2*n];
                bh[ni][0] = __float_as_uint(q0.x); bl[ni][0] = __float_as_uint(q0.y);
                bh[ni][1] = __float_as_uint(q1.x); bl[ni][1] = __float_as_uint(q1.y);
            }
#pragma unroll
            for (int mi = 0; mi < 4; mi++)
#pragma unroll
                for (int ni = 0; ni < 4; ni++) {
                    mma8(acc[mi][ni], ah[mi], bh[ni]);
                    mma8(acc[mi][ni], ah[mi], bl[ni]);
                    mma8(acc[mi][ni], al[mi], bh[ni]);
                }
        }
        __syncthreads();
    }

    // ---- epilogue: bias (+relu), float2 stores
#pragma unroll
    for (int mi = 0; mi < 4; mi++) {
#pragma unroll
        for (int ni = 0; ni < 4; ni++) {
            const int r = bm + wm + mi * 16 + grp;
            const int c = bn + wn + ni * 8 + tig * 2;
            float b0 = bias[c], b1 = bias[c + 1];
            float v0 = acc[mi][ni][0] + b0;
            float v1 = acc[mi][ni][1] + b1;
            float v2 = acc[mi][ni][2] + b0;
            float v3 = acc[mi][ni][3] + b1;
            if (RELU) {
                v0 = fmaxf(v0, 0.f); v1 = fmaxf(v1, 0.f);
                v2 = fmaxf(v2, 0.f); v3 = fmaxf(v3, 0.f);
            }
            *(float2*)&C[(size_t)r * Nc + c]       = make_float2(v0, v1);
            *(float2*)&C[(size_t)(r + 8) * Nc + c] = make_float2(v2, v3);
        }
    }
}

template<bool RELU>
__global__ void __launch_bounds__(128) gemm_tf32_kernel(
    const float* __restrict__ A, const float* __restrict__ B,
    const float* __restrict__ bias, float* __restrict__ C, int Nc, int K)
{
    gemm_tf32_core<RELU>(A, B, bias, C, Nc, K, blockIdx.y * GBM, blockIdx.x * GBN);
}

// Fused QKV: grid.x = 12 -> (which of Q/K/V) x (4 column blocks)
struct QKVArgs {
    const float* W[3];
    const float* b[3];
    float*       O[3];
};

__global__ void __launch_bounds__(128) qkv_gemm_kernel(
    const float* __restrict__ A, QKVArgs args, int Nc, int K)
{
    const int sel = blockIdx.x >> 2;
    const int bn  = (blockIdx.x & 3) * GBN;
    gemm_tf32_core<false>(A, args.W[sel], args.b[sel], args.O[sel],
                          Nc, K, blockIdx.y * GBM, bn);
}

// ---------------------------------------------------------------------------
// Edge attention bias: eatt[e,h] = edge_features[e,:] @ We[:,h] + be[h]
// float4-vectorized feature loads.
// ---------------------------------------------------------------------------
__global__ void edge_kernel(const float* __restrict__ ef,
                            const float* __restrict__ We,
                            const float* __restrict__ be,
                            float* __restrict__ eatt)
{
    __shared__ float sWe[EDIM*HH];   // 256 floats
    __shared__ float sbe[HH];
    if (threadIdx.x < EDIM*HH) sWe[threadIdx.x] = We[threadIdx.x];
    if (threadIdx.x < HH)      sbe[threadIdx.x] = be[threadIdx.x];
    __syncthreads();

    int e = blockIdx.x * blockDim.x + threadIdx.x;
    if (e >= EE) return;

    float acc[HH];
#pragma unroll
    for (int h = 0; h < HH; h++) acc[h] = sbe[h];

    const float4* row = (const float4*)(ef + (size_t)e * EDIM);
#pragma unroll
    for (int q = 0; q < EDIM/4; q++) {
        float4 v = row[q];
        const float xs[4] = {v.x, v.y, v.z, v.w};
#pragma unroll
        for (int j = 0; j < 4; j++) {
            float x = xs[j];
            const float* w = &sWe[(q*4 + j) * HH];
#pragma unroll
            for (int h = 0; h < HH; h++) acc[h] = fmaf(x, w[h], acc[h]);
        }
    }
#pragma unroll
    for (int h = 0; h < HH; h++) eatt[(size_t)e*HH + h] = acc[h];
}

// ---------------------------------------------------------------------------
// Sparse attention: one block per node, one warp per head.
// Dedup rule: among duplicate neighbors, keep the LAST occurrence.
// ---------------------------------------------------------------------------
__global__ void __launch_bounds__(HH*32) attn_kernel(
    const float* __restrict__ Q, const float* __restrict__ K,
    const float* __restrict__ V, const int* __restrict__ nbr,
    const float* __restrict__ eatt, float* __restrict__ out)
{
    const int n = blockIdx.x;
    __shared__ int snb[DEG];
    __shared__ int skeep[DEG];

    const int tid = threadIdx.x;
    if (tid < DEG) snb[tid] = nbr[n*DEG + tid];
    __syncthreads();
    if (tid < DEG) {
        int keep = 1;
        int m = snb[tid];
        for (int j = tid + 1; j < DEG; j++)
            if (snb[j] == m) keep = 0;
        skeep[tid] = keep;
    }
    __syncthreads();

    const int h    = tid >> 5;
    const int lane = tid & 31;
    const unsigned FULL = 0xffffffffu;

    const float q = Q[(size_t)n*HID + h*DH + lane];

    float sc = -1e30f;   // lane j<DEG holds score_j; others -inf
#pragma unroll
    for (int j = 0; j < DEG; j++) {
        if (skeep[j]) {
            float v = q * K[(size_t)snb[j]*HID + h*DH + lane];
#pragma unroll
            for (int o = 16; o > 0; o >>= 1)
                v += __shfl_xor_sync(FULL, v, o);
            v = v * 0.17677669529663687f + eatt[(size_t)(n*DEG + j)*HH + h];
            if (lane == j) sc = v;
        }
    }

    // softmax over the 32 lanes (inactive lanes carry -1e30 -> p=0)
    float m = sc;
#pragma unroll
    for (int o = 16; o > 0; o >>= 1)
        m = fmaxf(m, __shfl_xor_sync(FULL, m, o));
    float p = (sc > -1e29f) ? __expf(sc - m) : 0.f;
    float s = p;
#pragma unroll
    for (int o = 16; o > 0; o >>= 1)
        s += __shfl_xor_sync(FULL, s, o);
    p /= s;

    float acc = 0.f;
#pragma unroll
    for (int j = 0; j < DEG; j++) {
        if (skeep[j]) {
            float pj = __shfl_sync(FULL, p, j);
            acc = fmaf(pj, V[(size_t)snb[j]*HID + h*DH + lane], acc);
        }
    }
    out[(size_t)n*HID + h*DH + lane] = acc;
}

// ---------------------------------------------------------------------------
// Fused residual add + LayerNorm over HID=256. One block (256 thr) per row.
// ---------------------------------------------------------------------------
__global__ void __launch_bounds__(HID) add_ln_kernel(
    const float* __restrict__ a, const float* __restrict__ res,
    const float* __restrict__ g, const float* __restrict__ b,
    float* __restrict__ out)
{
    __shared__ float red[8];
    const int row = blockIdx.x;
    const int tid = threadIdx.x;
    const int lane = tid & 31, w = tid >> 5;
    const unsigned FULL = 0xffffffffu;

    float x = a[(size_t)row*HID + tid] + res[(size_t)row*HID + tid];

    // mean
    float v = x;
#pragma unroll
    for (int o = 16; o > 0; o >>= 1) v += __shfl_xor_sync(FULL, v, o);
    if (lane == 0) red[w] = v;
    __syncthreads();
    float t = (tid < 8) ? red[tid] : 0.f;
    if (w == 0) {
#pragma unroll
        for (int o = 4; o > 0; o >>= 1) t += __shfl_xor_sync(FULL, t, o);
        if (lane == 0) red[0] = t;
    }
    __syncthreads();
    float mu = red[0] * (1.f / HID);
    __syncthreads();

    // variance
    float d = x - mu;
    v = d * d;
#pragma unroll
    for (int o = 16; o > 0; o >>= 1) v += __shfl_xor_sync(FULL, v, o);
    if (lane == 0) red[w] = v;
    __syncthreads();
    t = (tid < 8) ? red[tid] : 0.f;
    if (w == 0) {
#pragma unroll
        for (int o = 4; o > 0; o >>= 1) t += __shfl_xor_sync(FULL, t, o);
        if (lane == 0) red[0] = t;
    }
    __syncthreads();
    float var = red[0] * (1.f / HID);

    out[(size_t)row*HID + tid] = d * rsqrtf(var + 1e-5f) * g[tid] + b[tid];
}

// ---------------------------------------------------------------------------
// Launch
// ---------------------------------------------------------------------------
extern "C" void kernel_launch(void* const* d_in, const int* in_sizes, int n_in,
                              void* d_out, int out_size)
{
    const float* node = (const float*)d_in[0];
    const int*   nbr  = (const int*)  d_in[1];
    const float* ef   = (const float*)d_in[2];
    const float* Wq   = (const float*)d_in[3];
    const float* bq   = (const float*)d_in[4];
    const float* Wk   = (const float*)d_in[5];
    const float* bk   = (const float*)d_in[6];
    const float* Wv   = (const float*)d_in[7];
    const float* bv   = (const float*)d_in[8];
    const float* We   = (const float*)d_in[9];
    const float* be   = (const float*)d_in[10];
    const float* Wo   = (const float*)d_in[11];
    const float* bo   = (const float*)d_in[12];
    const float* ln1g = (const float*)d_in[13];
    const float* ln1b = (const float*)d_in[14];
    const float* ln2g = (const float*)d_in[15];
    const float* ln2b = (const float*)d_in[16];
    const float* Wf1  = (const float*)d_in[17];
    const float* bf1  = (const float*)d_in[18];
    const float* Wf2  = (const float*)d_in[19];
    const float* bf2  = (const float*)d_in[20];
    float* out = (float*)d_out;

    static float *Qd = nullptr, *Kd, *Vd, *eattd, *attnd, *t1d, *x1d, *fd, *t2d;
    if (!Qd) {
        cudaGetSymbolAddress((void**)&Qd,    g_Q);
        cudaGetSymbolAddress((void**)&Kd,    g_K);
        cudaGetSymbolAddress((void**)&Vd,    g_V);
        cudaGetSymbolAddress((void**)&eattd, g_eatt);
        cudaGetSymbolAddress((void**)&attnd, g_attn);
        cudaGetSymbolAddress((void**)&t1d,   g_t1);
        cudaGetSymbolAddress((void**)&x1d,   g_x1);
        cudaGetSymbolAddress((void**)&fd,    g_f);
        cudaGetSymbolAddress((void**)&t2d,   g_t2);
    }

    // Fused QKV projections (tensor cores, split-tf32)
    QKVArgs qa;
    qa.W[0] = Wq; qa.W[1] = Wk; qa.W[2] = Wv;
    qa.b[0] = bq; qa.b[1] = bk; qa.b[2] = bv;
    qa.O[0] = Qd; qa.O[1] = Kd; qa.O[2] = Vd;
    qkv_gemm_kernel<<<dim3(12, NN/GBM), 128>>>(node, qa, HID, HID);

    // Edge bias
    edge_kernel<<<(EE + 255)/256, 256>>>(ef, We, be, eattd);

    // Sparse attention
    attn_kernel<<<NN, HH*32>>>(Qd, Kd, Vd, nbr, eattd, attnd);

    // Output projection + residual + LN1
    gemm_tf32_kernel<false><<<dim3(HID/GBN, NN/GBM), 128>>>(attnd, Wo, bo, t1d, HID, HID);
    add_ln_kernel<<<NN, HID>>>(t1d, node, ln1g, ln1b, x1d);

    // FFN
    gemm_tf32_kernel<true ><<<dim3(FFN/GBN, NN/GBM), 128>>>(x1d, Wf1, bf1, fd, FFN, HID);
    gemm_tf32_kernel<false><<<dim3(HID/GBN, NN/GBM), 128>>>(fd, Wf2, bf2, t2d, HID, FFN);
    add_ln_kernel<<<NN, HID>>>(t2d, x1d, ln2g, ln2b, out);
}

// round 4
// speedup vs baseline: 1.7677x; 1.7354x over previous
#include <cuda_runtime.h>
#include <cuda_bf16.h>
#include <math.h>
#include <stdint.h>

// Problem constants
#define NN   3072
#define HH   8
#define DH   32
#define HID  256
#define DEG  16
#define EE   (NN*DEG)      // 49152
#define EDIM 32
#define FFN  1024

// ---------------------------------------------------------------------------
// Scratch (no allocations allowed -> __device__ globals)
// ---------------------------------------------------------------------------
__device__ float g_Q[NN*HID];
__device__ float g_K[NN*HID];
__device__ float g_V[NN*HID];
__device__ float g_eatt[EE*HH];
__device__ float g_attn[NN*HID];
__device__ float g_t1[NN*HID];
__device__ float g_x1[NN*HID];
__device__ float g_f[NN*FFN];
__device__ float g_t2[NN*HID];

// ---------------------------------------------------------------------------
// Split-BF16 GEMM via mma.sync.m16n8k16 (fp32-accurate: hh + hl + lh)
// Block tile 64x64, BK=32, 128 threads (4 warps, 2x2), warp tile 32x32.
// Smem: (hi2, lo2) bf16x2 pairs in uint2, layout [k2][row], stride 68.
// Software-pipelined: next tile's global loads issued before compute.
// ---------------------------------------------------------------------------
#define GBM 64
#define GBN 64
#define GBK 32
#define KP  16      // k-pairs per stage
#define SSTR 68     // uint2 stride

__device__ __forceinline__ uint32_t b2u(__nv_bfloat162 v) {
    return *reinterpret_cast<uint32_t*>(&v);
}

__device__ __forceinline__ uint2 split_pair(float x, float y) {
    __nv_bfloat162 h = __floats2bfloat162_rn(x, y);
    float rx = x - __bfloat162float(h.x);
    float ry = y - __bfloat162float(h.y);
    __nv_bfloat162 l = __floats2bfloat162_rn(rx, ry);
    return make_uint2(b2u(h), b2u(l));
}

__device__ __forceinline__ void mma16(float* c, const uint32_t* a, const uint32_t* b) {
    asm volatile(
        "mma.sync.aligned.m16n8k16.row.col.f32.bf16.bf16.f32 "
        "{%0,%1,%2,%3}, {%4,%5,%6,%7}, {%8,%9}, {%0,%1,%2,%3};\n"
        : "+f"(c[0]), "+f"(c[1]), "+f"(c[2]), "+f"(c[3])
        : "r"(a[0]), "r"(a[1]), "r"(a[2]), "r"(a[3]), "r"(b[0]), "r"(b[1]));
}

template<bool RELU>
__device__ __forceinline__ void gemm_core(
    const float* __restrict__ A, const float* __restrict__ B,
    const float* __restrict__ bias, float* __restrict__ C,
    int Nc, int K, int bm, int bn)
{
    __shared__ uint2 As[KP][SSTR];
    __shared__ uint2 Bs[KP][SSTR];

    const int tid  = threadIdx.x;
    const int lane = tid & 31;
    const int warp = tid >> 5;
    const int wm   = (warp & 1) * 32;
    const int wn   = (warp >> 1) * 32;
    const int grp  = lane >> 2;
    const int tig  = lane & 3;

    float acc[2][4][4] = {};
    float4 pa[4];
    float2 pb[4][2];

#define LOAD_G(k0)                                                              \
    {                                                                           \
        _Pragma("unroll")                                                       \
        for (int it = 0; it < 4; it++) {                                        \
            int idx = tid + it * 128;                                           \
            int row = idx >> 3, c4 = idx & 7;                                   \
            pa[it] = *(const float4*)(A + (size_t)(bm + row) * K + (k0) + c4*4);\
            int k2 = idx >> 5, cp = idx & 31;                                   \
            pb[it][0] = *(const float2*)(B + (size_t)((k0) + 2*k2    ) * Nc + bn + 2*cp); \
            pb[it][1] = *(const float2*)(B + (size_t)((k0) + 2*k2 + 1) * Nc + bn + 2*cp); \
        }                                                                       \
    }

#define STS_TILE()                                                              \
    {                                                                           \
        _Pragma("unroll")                                                       \
        for (int it = 0; it < 4; it++) {                                        \
            int idx = tid + it * 128;                                           \
            int row = idx >> 3, c4 = idx & 7;                                   \
            As[2*c4    ][row] = split_pair(pa[it].x, pa[it].y);                 \
            As[2*c4 + 1][row] = split_pair(pa[it].z, pa[it].w);                 \
            int k2 = idx >> 5, cp = idx & 31;                                   \
            Bs[k2][2*cp    ] = split_pair(pb[it][0].x, pb[it][1].x);            \
            Bs[k2][2*cp + 1] = split_pair(pb[it][0].y, pb[it][1].y);            \
        }                                                                       \
    }

#define COMPUTE()                                                               \
    {                                                                           \
        _Pragma("unroll")                                                       \
        for (int s = 0; s < 2; s++) {                                           \
            const int k2a = s*8 + tig, k2b = s*8 + tig + 4;                     \
            uint32_t ah[2][4], al[2][4], bh[4][2], bl[4][2];                    \
            _Pragma("unroll")                                                   \
            for (int mi = 0; mi < 2; mi++) {                                    \
                int r = wm + mi*16 + grp;                                       \
                uint2 e0 = As[k2a][r], e1 = As[k2a][r+8];                       \
                uint2 e2 = As[k2b][r], e3 = As[k2b][r+8];                       \
                ah[mi][0]=e0.x; ah[mi][1]=e1.x; ah[mi][2]=e2.x; ah[mi][3]=e3.x; \
                al[mi][0]=e0.y; al[mi][1]=e1.y; al[mi][2]=e2.y; al[mi][3]=e3.y; \
            }                                                                   \
            _Pragma("unroll")                                                   \
            for (int ni = 0; ni < 4; ni++) {                                    \
                int c = wn + ni*8 + grp;                                        \
                uint2 f0 = Bs[k2a][c], f1 = Bs[k2b][c];                         \
                bh[ni][0]=f0.x; bh[ni][1]=f1.x;                                 \
                bl[ni][0]=f0.y; bl[ni][1]=f1.y;                                 \
            }                                                                   \
            _Pragma("unroll")                                                   \
            for (int mi = 0; mi < 2; mi++)                                      \
                _Pragma("unroll")                                               \
                for (int ni = 0; ni < 4; ni++) {                                \
                    mma16(acc[mi][ni], ah[mi], bh[ni]);                         \
                    mma16(acc[mi][ni], ah[mi], bl[ni]);                         \
                    mma16(acc[mi][ni], al[mi], bh[ni]);                         \
                }                                                               \
        }                                                                       \
    }

    LOAD_G(0);
    STS_TILE();
    __syncthreads();
#pragma unroll 1
    for (int k0 = GBK; k0 < K; k0 += GBK) {
        LOAD_G(k0);       // prefetch next tile into registers
        COMPUTE();        // consume current smem tile
        __syncthreads();
        STS_TILE();
        __syncthreads();
    }
    COMPUTE();

    // epilogue: bias (+relu)
#pragma unroll
    for (int mi = 0; mi < 2; mi++) {
#pragma unroll
        for (int ni = 0; ni < 4; ni++) {
            int r = bm + wm + mi*16 + grp;
            int c = bn + wn + ni*8 + tig*2;
            float b0 = bias[c], b1 = bias[c+1];
            float v0 = acc[mi][ni][0] + b0;
            float v1 = acc[mi][ni][1] + b1;
            float v2 = acc[mi][ni][2] + b0;
            float v3 = acc[mi][ni][3] + b1;
            if (RELU) {
                v0 = fmaxf(v0, 0.f); v1 = fmaxf(v1, 0.f);
                v2 = fmaxf(v2, 0.f); v3 = fmaxf(v3, 0.f);
            }
            *(float2*)&C[(size_t)r * Nc + c]       = make_float2(v0, v1);
            *(float2*)&C[(size_t)(r + 8) * Nc + c] = make_float2(v2, v3);
        }
    }
#undef LOAD_G
#undef STS_TILE
#undef COMPUTE
}

template<bool RELU>
__global__ void __launch_bounds__(128) gemm_kernel(
    const float* __restrict__ A, const float* __restrict__ B,
    const float* __restrict__ bias, float* __restrict__ C, int Nc, int K)
{
    gemm_core<RELU>(A, B, bias, C, Nc, K, blockIdx.y * GBM, blockIdx.x * GBN);
}

// Fused QKV: grid.x = 12 -> (which of Q/K/V) x (4 column blocks)
struct QKVArgs {
    const float* W[3];
    const float* b[3];
    float*       O[3];
};

__global__ void __launch_bounds__(128) qkv_gemm_kernel(
    const float* __restrict__ A, QKVArgs args, int Nc, int K)
{
    const int sel = blockIdx.x >> 2;
    const int bn  = (blockIdx.x & 3) * GBN;
    gemm_core<false>(A, args.W[sel], args.b[sel], args.O[sel],
                     Nc, K, blockIdx.y * GBM, bn);
}

// ---------------------------------------------------------------------------
// Edge attention bias: eatt[e,h] = edge_features[e,:] @ We[:,h] + be[h]
// ---------------------------------------------------------------------------
__global__ void edge_kernel(const float* __restrict__ ef,
                            const float* __restrict__ We,
                            const float* __restrict__ be,
                            float* __restrict__ eatt)
{
    __shared__ float sWe[EDIM*HH];
    __shared__ float sbe[HH];
    if (threadIdx.x < EDIM*HH) sWe[threadIdx.x] = We[threadIdx.x];
    if (threadIdx.x < HH)      sbe[threadIdx.x] = be[threadIdx.x];
    __syncthreads();

    int e = blockIdx.x * blockDim.x + threadIdx.x;
    if (e >= EE) return;

    float acc[HH];
#pragma unroll
    for (int h = 0; h < HH; h++) acc[h] = sbe[h];

    const float4* row = (const float4*)(ef + (size_t)e * EDIM);
#pragma unroll
    for (int q = 0; q < EDIM/4; q++) {
        float4 v = row[q];
        const float xs[4] = {v.x, v.y, v.z, v.w};
#pragma unroll
        for (int j = 0; j < 4; j++) {
            float x = xs[j];
            const float* w = &sWe[(q*4 + j) * HH];
#pragma unroll
            for (int h = 0; h < HH; h++) acc[h] = fmaf(x, w[h], acc[h]);
        }
    }
#pragma unroll
    for (int h = 0; h < HH; h++) eatt[(size_t)e*HH + h] = acc[h];
}

// ---------------------------------------------------------------------------
// Sparse attention: one block per node, one warp per head.
// Dedup: keep LAST occurrence of duplicate neighbors (XLA scatter semantics).
// ---------------------------------------------------------------------------
__global__ void __launch_bounds__(HH*32) attn_kernel(
    const float* __restrict__ Q, const float* __restrict__ K,
    const float* __restrict__ V, const int* __restrict__ nbr,
    const float* __restrict__ eatt, float* __restrict__ out)
{
    const int n = blockIdx.x;
    __shared__ int snb[DEG];
    __shared__ int skeep[DEG];

    const int tid = threadIdx.x;
    if (tid < DEG) snb[tid] = nbr[n*DEG + tid];
    __syncthreads();
    if (tid < DEG) {
        int keep = 1;
        int m = snb[tid];
        for (int j = tid + 1; j < DEG; j++)
            if (snb[j] == m) keep = 0;
        skeep[tid] = keep;
    }
    __syncthreads();

    const int h    = tid >> 5;
    const int lane = tid & 31;
    const unsigned FULL = 0xffffffffu;

    const float q = Q[(size_t)n*HID + h*DH + lane];

    float sc = -1e30f;
#pragma unroll
    for (int j = 0; j < DEG; j++) {
        if (skeep[j]) {
            float v = q * K[(size_t)snb[j]*HID + h*DH + lane];
#pragma unroll
            for (int o = 16; o > 0; o >>= 1)
                v += __shfl_xor_sync(FULL, v, o);
            v = v * 0.17677669529663687f + eatt[(size_t)(n*DEG + j)*HH + h];
            if (lane == j) sc = v;
        }
    }

    float m = sc;
#pragma unroll
    for (int o = 16; o > 0; o >>= 1)
        m = fmaxf(m, __shfl_xor_sync(FULL, m, o));
    float p = (sc > -1e29f) ? __expf(sc - m) : 0.f;
    float s = p;
#pragma unroll
    for (int o = 16; o > 0; o >>= 1)
        s += __shfl_xor_sync(FULL, s, o);
    p /= s;

    float acc = 0.f;
#pragma unroll
    for (int j = 0; j < DEG; j++) {
        if (skeep[j]) {
            float pj = __shfl_sync(FULL, p, j);
            acc = fmaf(pj, V[(size_t)snb[j]*HID + h*DH + lane], acc);
        }
    }
    out[(size_t)n*HID + h*DH + lane] = acc;
}

// ---------------------------------------------------------------------------
// Fused residual add + LayerNorm over HID=256. One block (256 thr) per row.
// ---------------------------------------------------------------------------
__global__ void __launch_bounds__(HID) add_ln_kernel(
    const float* __restrict__ a, const float* __restrict__ res,
    const float* __restrict__ g, const float* __restrict__ b,
    float* __restrict__ out)
{
    __shared__ float red[8];
    const int row = blockIdx.x;
    const int tid = threadIdx.x;
    const int lane = tid & 31, w = tid >> 5;
    const unsigned FULL = 0xffffffffu;

    float x = a[(size_t)row*HID + tid] + res[(size_t)row*HID + tid];

    float v = x;
#pragma unroll
    for (int o = 16; o > 0; o >>= 1) v += __shfl_xor_sync(FULL, v, o);
    if (lane == 0) red[w] = v;
    __syncthreads();
    float t = (tid < 8) ? red[tid] : 0.f;
    if (w == 0) {
#pragma unroll
        for (int o = 4; o > 0; o >>= 1) t += __shfl_xor_sync(FULL, t, o);
        if (lane == 0) red[0] = t;
    }
    __syncthreads();
    float mu = red[0] * (1.f / HID);
    __syncthreads();

    float d = x - mu;
    v = d * d;
#pragma unroll
    for (int o = 16; o > 0; o >>= 1) v += __shfl_xor_sync(FULL, v, o);
    if (lane == 0) red[w] = v;
    __syncthreads();
    t = (tid < 8) ? red[tid] : 0.f;
    if (w == 0) {
#pragma unroll
        for (int o = 4; o > 0; o >>= 1) t += __shfl_xor_sync(FULL, t, o);
        if (lane == 0) red[0] = t;
    }
    __syncthreads();
    float var = red[0] * (1.f / HID);

    out[(size_t)row*HID + tid] = d * rsqrtf(var + 1e-5f) * g[tid] + b[tid];
}

// ---------------------------------------------------------------------------
// Launch
// ---------------------------------------------------------------------------
extern "C" void kernel_launch(void* const* d_in, const int* in_sizes, int n_in,
                              void* d_out, int out_size)
{
    const float* node = (const float*)d_in[0];
    const int*   nbr  = (const int*)  d_in[1];
    const float* ef   = (const float*)d_in[2];
    const float* Wq   = (const float*)d_in[3];
    const float* bq   = (const float*)d_in[4];
    const float* Wk   = (const float*)d_in[5];
    const float* bk   = (const float*)d_in[6];
    const float* Wv   = (const float*)d_in[7];
    const float* bv   = (const float*)d_in[8];
    const float* We   = (const float*)d_in[9];
    const float* be   = (const float*)d_in[10];
    const float* Wo   = (const float*)d_in[11];
    const float* bo   = (const float*)d_in[12];
    const float* ln1g = (const float*)d_in[13];
    const float* ln1b = (const float*)d_in[14];
    const float* ln2g = (const float*)d_in[15];
    const float* ln2b = (const float*)d_in[16];
    const float* Wf1  = (const float*)d_in[17];
    const float* bf1  = (const float*)d_in[18];
    const float* Wf2  = (const float*)d_in[19];
    const float* bf2  = (const float*)d_in[20];
    float* out = (float*)d_out;

    static float *Qd = nullptr, *Kd, *Vd, *eattd, *attnd, *t1d, *x1d, *fd, *t2d;
    if (!Qd) {
        cudaGetSymbolAddress((void**)&Qd,    g_Q);
        cudaGetSymbolAddress((void**)&Kd,    g_K);
        cudaGetSymbolAddress((void**)&Vd,    g_V);
        cudaGetSymbolAddress((void**)&eattd, g_eatt);
        cudaGetSymbolAddress((void**)&attnd, g_attn);
        cudaGetSymbolAddress((void**)&t1d,   g_t1);
        cudaGetSymbolAddress((void**)&x1d,   g_x1);
        cudaGetSymbolAddress((void**)&fd,    g_f);
        cudaGetSymbolAddress((void**)&t2d,   g_t2);
    }

    // Fused QKV projections
    QKVArgs qa;
    qa.W[0] = Wq; qa.W[1] = Wk; qa.W[2] = Wv;
    qa.b[0] = bq; qa.b[1] = bk; qa.b[2] = bv;
    qa.O[0] = Qd; qa.O[1] = Kd; qa.O[2] = Vd;
    qkv_gemm_kernel<<<dim3(12, NN/GBM), 128>>>(node, qa, HID, HID);

    // Edge bias
    edge_kernel<<<(EE + 255)/256, 256>>>(ef, We, be, eattd);

    // Sparse attention
    attn_kernel<<<NN, HH*32>>>(Qd, Kd, Vd, nbr, eattd, attnd);

    // Output projection + residual + LN1
    gemm_kernel<false><<<dim3(HID/GBN, NN/GBM), 128>>>(attnd, Wo, bo, t1d, HID, HID);
    add_ln_kernel<<<NN, HID>>>(t1d, node, ln1g, ln1b, x1d);

    // FFN
    gemm_kernel<true ><<<dim3(FFN/GBN, NN/GBM), 128>>>(x1d, Wf1, bf1, fd, FFN, HID);
    gemm_kernel<false><<<dim3(HID/GBN, NN/GBM), 128>>>(fd, Wf2, bf2, t2d, HID, FFN);
    add_ln_kernel<<<NN, HID>>>(t2d, x1d, ln2g, ln2b, out);
}

// round 5
// speedup vs baseline: 1.9736x; 1.1165x over previous
#include <cuda_runtime.h>
#include <cuda_bf16.h>
#include <math.h>
#include <stdint.h>

// Problem constants
#define NN   3072
#define HH   8
#define DH   32
#define HID  256
#define DEG  16
#define EE   (NN*DEG)      // 49152
#define EDIM 32
#define FFN  1024

// ---------------------------------------------------------------------------
// Scratch (no allocations allowed -> __device__ globals)
// ---------------------------------------------------------------------------
__device__ float g_Q[NN*HID];
__device__ float g_K[NN*HID];
__device__ float g_V[NN*HID];
__device__ float g_eatt[EE*HH];
__device__ float g_attn[NN*HID];
__device__ float g_x1[NN*HID];
__device__ float g_f[NN*FFN];
__device__ float g_part[4][NN*HID];   // split-K partials

struct Parts4 { float* p[4]; };

// ---------------------------------------------------------------------------
// Split-BF16 GEMM via mma.sync.m16n8k16 (fp32-accurate: hh + hl + lh)
// Block tile 64x64, BK=32, 128 threads (4 warps, 2x2), warp tile 32x32.
// Double-buffered smem; register prefetch of next global tile.
// ---------------------------------------------------------------------------
#define GBM 64
#define GBN 64
#define GBK 32
#define KP  16      // k-pairs per stage
#define SSTR 68     // uint2 stride

__device__ __forceinline__ uint32_t b2u(__nv_bfloat162 v) {
    return *reinterpret_cast<uint32_t*>(&v);
}

__device__ __forceinline__ uint2 split_pair(float x, float y) {
    __nv_bfloat162 h = __floats2bfloat162_rn(x, y);
    float rx = x - __bfloat162float(h.x);
    float ry = y - __bfloat162float(h.y);
    __nv_bfloat162 l = __floats2bfloat162_rn(rx, ry);
    return make_uint2(b2u(h), b2u(l));
}

__device__ __forceinline__ void mma16(float* c, const uint32_t* a, const uint32_t* b) {
    asm volatile(
        "mma.sync.aligned.m16n8k16.row.col.f32.bf16.bf16.f32 "
        "{%0,%1,%2,%3}, {%4,%5,%6,%7}, {%8,%9}, {%0,%1,%2,%3};\n"
        : "+f"(c[0]), "+f"(c[1]), "+f"(c[2]), "+f"(c[3])
        : "r"(a[0]), "r"(a[1]), "r"(a[2]), "r"(a[3]), "r"(b[0]), "r"(b[1]));
}

// BIAS: add bias in epilogue. RELU: clamp. If !BIAS, raw accum store (partials).
template<bool RELU, bool BIAS>
__device__ __forceinline__ void gemm_core(
    const float* __restrict__ A, const float* __restrict__ B,
    const float* __restrict__ bias, float* __restrict__ C,
    int Nc, int K, int kbeg, int kend, int bm, int bn)
{
    __shared__ uint2 As[2][KP][SSTR];
    __shared__ uint2 Bs[2][KP][SSTR];

    const int tid  = threadIdx.x;
    const int lane = tid & 31;
    const int warp = tid >> 5;
    const int wm   = (warp & 1) * 32;
    const int wn   = (warp >> 1) * 32;
    const int grp  = lane >> 2;
    const int tig  = lane & 3;

    float acc[2][4][4] = {};
    float4 pa[4];
    float2 pb[4][2];

#define LOAD_G(k0)                                                              \
    {                                                                           \
        _Pragma("unroll")                                                       \
        for (int it = 0; it < 4; it++) {                                        \
            int idx = tid + it * 128;                                           \
            int row = idx >> 3, c4 = idx & 7;                                   \
            pa[it] = *(const float4*)(A + (size_t)(bm + row) * K + (k0) + c4*4);\
            int k2 = idx >> 5, cp = idx & 31;                                   \
            pb[it][0] = *(const float2*)(B + (size_t)((k0) + 2*k2    ) * Nc + bn + 2*cp); \
            pb[it][1] = *(const float2*)(B + (size_t)((k0) + 2*k2 + 1) * Nc + bn + 2*cp); \
        }                                                                       \
    }

#define STS_TILE(bf)                                                            \
    {                                                                           \
        _Pragma("unroll")                                                       \
        for (int it = 0; it < 4; it++) {                                        \
            int idx = tid + it * 128;                                           \
            int row = idx >> 3, c4 = idx & 7;                                   \
            As[bf][2*c4    ][row] = split_pair(pa[it].x, pa[it].y);             \
            As[bf][2*c4 + 1][row] = split_pair(pa[it].z, pa[it].w);             \
            int k2 = idx >> 5, cp = idx & 31;                                   \
            Bs[bf][k2][2*cp    ] = split_pair(pb[it][0].x, pb[it][1].x);        \
            Bs[bf][k2][2*cp + 1] = split_pair(pb[it][0].y, pb[it][1].y);        \
        }                                                                       \
    }

#define COMPUTE(bf)                                                             \
    {                                                                           \
        _Pragma("unroll")                                                       \
        for (int s = 0; s < 2; s++) {                                           \
            const int k2a = s*8 + tig, k2b = s*8 + tig + 4;                     \
            uint32_t ah[2][4], al[2][4], bh[4][2], bl[4][2];                    \
            _Pragma("unroll")                                                   \
            for (int mi = 0; mi < 2; mi++) {                                    \
                int r = wm + mi*16 + grp;                                       \
                uint2 e0 = As[bf][k2a][r], e1 = As[bf][k2a][r+8];               \
                uint2 e2 = As[bf][k2b][r], e3 = As[bf][k2b][r+8];               \
                ah[mi][0]=e0.x; ah[mi][1]=e1.x; ah[mi][2]=e2.x; ah[mi][3]=e3.x; \
                al[mi][0]=e0.y; al[mi][1]=e1.y; al[mi][2]=e2.y; al[mi][3]=e3.y; \
            }                                                                   \
            _Pragma("unroll")                                                   \
            for (int ni = 0; ni < 4; ni++) {                                    \
                int c = wn + ni*8 + grp;                                        \
                uint2 f0 = Bs[bf][k2a][c], f1 = Bs[bf][k2b][c];                 \
                bh[ni][0]=f0.x; bh[ni][1]=f1.x;                                 \
                bl[ni][0]=f0.y; bl[ni][1]=f1.y;                                 \
            }                                                                   \
            _Pragma("unroll")                                                   \
            for (int mi = 0; mi < 2; mi++)                                      \
                _Pragma("unroll")                                               \
                for (int ni = 0; ni < 4; ni++) {                                \
                    mma16(acc[mi][ni], ah[mi], bh[ni]);                         \
                    mma16(acc[mi][ni], ah[mi], bl[ni]);                         \
                    mma16(acc[mi][ni], al[mi], bh[ni]);                         \
                }                                                               \
        }                                                                       \
    }

    LOAD_G(kbeg);
    STS_TILE(0);
    __syncthreads();
    int buf = 0;
#pragma unroll 1
    for (int k0 = kbeg + GBK; k0 < kend; k0 += GBK) {
        LOAD_G(k0);           // prefetch next tile into registers
        COMPUTE(buf);         // consume current smem buffer
        STS_TILE(buf ^ 1);    // fill other buffer
        __syncthreads();
        buf ^= 1;
    }
    COMPUTE(buf);

    // epilogue
#pragma unroll
    for (int mi = 0; mi < 2; mi++) {
#pragma unroll
        for (int ni = 0; ni < 4; ni++) {
            int r = bm + wm + mi*16 + grp;
            int c = bn + wn + ni*8 + tig*2;
            float v0 = acc[mi][ni][0];
            float v1 = acc[mi][ni][1];
            float v2 = acc[mi][ni][2];
            float v3 = acc[mi][ni][3];
            if (BIAS) {
                float b0 = bias[c], b1 = bias[c+1];
                v0 += b0; v1 += b1; v2 += b0; v3 += b1;
            }
            if (RELU) {
                v0 = fmaxf(v0, 0.f); v1 = fmaxf(v1, 0.f);
                v2 = fmaxf(v2, 0.f); v3 = fmaxf(v3, 0.f);
            }
            *(float2*)&C[(size_t)r * Nc + c]       = make_float2(v0, v1);
            *(float2*)&C[(size_t)(r + 8) * Nc + c] = make_float2(v2, v3);
        }
    }
#undef LOAD_G
#undef STS_TILE
#undef COMPUTE
}

template<bool RELU>
__global__ void __launch_bounds__(128, 4) gemm_kernel(
    const float* __restrict__ A, const float* __restrict__ B,
    const float* __restrict__ bias, float* __restrict__ C, int Nc, int K)
{
    gemm_core<RELU, true>(A, B, bias, C, Nc, K, 0, K,
                          blockIdx.y * GBM, blockIdx.x * GBN);
}

// Split-K partial GEMM: blockIdx.z selects k-slice and output partial buffer.
__global__ void __launch_bounds__(128, 4) gemm_split_kernel(
    const float* __restrict__ A, const float* __restrict__ B,
    Parts4 parts, int Nc, int K, int ksplit)
{
    const int z = blockIdx.z;
    gemm_core<false, false>(A, B, nullptr, parts.p[z], Nc, K,
                            z * ksplit, (z + 1) * ksplit,
                            blockIdx.y * GBM, blockIdx.x * GBN);
}

// Fused QKV: grid.x = 12 -> (which of Q/K/V) x (4 column blocks)
struct QKVArgs {
    const float* W[3];
    const float* b[3];
    float*       O[3];
};

__global__ void __launch_bounds__(128, 4) qkv_gemm_kernel(
    const float* __restrict__ A, QKVArgs args, int Nc, int K)
{
    const int sel = blockIdx.x >> 2;
    const int bn  = (blockIdx.x & 3) * GBN;
    gemm_core<false, true>(A, args.W[sel], args.b[sel], args.O[sel],
                           Nc, K, 0, K, blockIdx.y * GBM, bn);
}

// ---------------------------------------------------------------------------
// Edge attention bias: eatt[e,h] = edge_features[e,:] @ We[:,h] + be[h]
// ---------------------------------------------------------------------------
__global__ void edge_kernel(const float* __restrict__ ef,
                            const float* __restrict__ We,
                            const float* __restrict__ be,
                            float* __restrict__ eatt)
{
    __shared__ float sWe[EDIM*HH];
    __shared__ float sbe[HH];
    if (threadIdx.x < EDIM*HH) sWe[threadIdx.x] = We[threadIdx.x];
    if (threadIdx.x < HH)      sbe[threadIdx.x] = be[threadIdx.x];
    __syncthreads();

    int e = blockIdx.x * blockDim.x + threadIdx.x;
    if (e >= EE) return;

    float acc[HH];
#pragma unroll
    for (int h = 0; h < HH; h++) acc[h] = sbe[h];

    const float4* row = (const float4*)(ef + (size_t)e * EDIM);
#pragma unroll
    for (int q = 0; q < EDIM/4; q++) {
        float4 v = row[q];
        const float xs[4] = {v.x, v.y, v.z, v.w};
#pragma unroll
        for (int j = 0; j < 4; j++) {
            float x = xs[j];
            const float* w = &sWe[(q*4 + j) * HH];
#pragma unroll
            for (int h = 0; h < HH; h++) acc[h] = fmaf(x, w[h], acc[h]);
        }
    }
    float4* o = (float4*)(eatt + (size_t)e*HH);
    o[0] = make_float4(acc[0], acc[1], acc[2], acc[3]);
    o[1] = make_float4(acc[4], acc[5], acc[6], acc[7]);
}

// ---------------------------------------------------------------------------
// Sparse attention: one block per node, one warp per head.
// Dedup: keep LAST occurrence of duplicate neighbors (XLA scatter semantics).
// ---------------------------------------------------------------------------
__global__ void __launch_bounds__(HH*32) attn_kernel(
    const float* __restrict__ Q, const float* __restrict__ K,
    const float* __restrict__ V, const int* __restrict__ nbr,
    const float* __restrict__ eatt, float* __restrict__ out)
{
    const int n = blockIdx.x;
    __shared__ int snb[DEG];
    __shared__ int skeep[DEG];

    const int tid = threadIdx.x;
    if (tid < DEG) snb[tid] = nbr[n*DEG + tid];
    __syncthreads();
    if (tid < DEG) {
        int keep = 1;
        int m = snb[tid];
        for (int j = tid + 1; j < DEG; j++)
            if (snb[j] == m) keep = 0;
        skeep[tid] = keep;
    }
    __syncthreads();

    const int h    = tid >> 5;
    const int lane = tid & 31;
    const unsigned FULL = 0xffffffffu;

    const float q = Q[(size_t)n*HID + h*DH + lane];

    float sc = -1e30f;
#pragma unroll
    for (int j = 0; j < DEG; j++) {
        if (skeep[j]) {
            float v = q * K[(size_t)snb[j]*HID + h*DH + lane];
#pragma unroll
            for (int o = 16; o > 0; o >>= 1)
                v += __shfl_xor_sync(FULL, v, o);
            v = v * 0.17677669529663687f + eatt[(size_t)(n*DEG + j)*HH + h];
            if (lane == j) sc = v;
        }
    }

    float m = sc;
#pragma unroll
    for (int o = 16; o > 0; o >>= 1)
        m = fmaxf(m, __shfl_xor_sync(FULL, m, o));
    float p = (sc > -1e29f) ? __expf(sc - m) : 0.f;
    float s = p;
#pragma unroll
    for (int o = 16; o > 0; o >>= 1)
        s += __shfl_xor_sync(FULL, s, o);
    p /= s;

    float acc = 0.f;
#pragma unroll
    for (int j = 0; j < DEG; j++) {
        if (skeep[j]) {
            float pj = __shfl_sync(FULL, p, j);
            acc = fmaf(pj, V[(size_t)snb[j]*HID + h*DH + lane], acc);
        }
    }
    out[(size_t)n*HID + h*DH + lane] = acc;
}

// ---------------------------------------------------------------------------
// Fused: sum of P split-K partials + bias + residual, then LayerNorm.
// One block (256 thr) per row.
// ---------------------------------------------------------------------------
template<int P>
__global__ void __launch_bounds__(HID) add_ln_multi(
    Parts4 parts, const float* __restrict__ bias,
    const float* __restrict__ res,
    const float* __restrict__ g, const float* __restrict__ b,
    float* __restrict__ out)
{
    __shared__ float red[8];
    const int row = blockIdx.x;
    const int tid = threadIdx.x;
    const int lane = tid & 31, w = tid >> 5;
    const unsigned FULL = 0xffffffffu;
    const size_t off = (size_t)row*HID + tid;

    float x = bias[tid] + res[off];
#pragma unroll
    for (int p = 0; p < P; p++) x += parts.p[p][off];

    float v = x;
#pragma unroll
    for (int o = 16; o > 0; o >>= 1) v += __shfl_xor_sync(FULL, v, o);
    if (lane == 0) red[w] = v;
    __syncthreads();
    float t = (tid < 8) ? red[tid] : 0.f;
    if (w == 0) {
#pragma unroll
        for (int o = 4; o > 0; o >>= 1) t += __shfl_xor_sync(FULL, t, o);
        if (lane == 0) red[0] = t;
    }
    __syncthreads();
    float mu = red[0] * (1.f / HID);
    __syncthreads();

    float d = x - mu;
    v = d * d;
#pragma unroll
    for (int o = 16; o > 0; o >>= 1) v += __shfl_xor_sync(FULL, v, o);
    if (lane == 0) red[w] = v;
    __syncthreads();
    t = (tid < 8) ? red[tid] : 0.f;
    if (w == 0) {
#pragma unroll
        for (int o = 4; o > 0; o >>= 1) t += __shfl_xor_sync(FULL, t, o);
        if (lane == 0) red[0] = t;
    }
    __syncthreads();
    float var = red[0] * (1.f / HID);

    out[off] = d * rsqrtf(var + 1e-5f) * g[tid] + b[tid];
}

// ---------------------------------------------------------------------------
// Launch
// ---------------------------------------------------------------------------
extern "C" void kernel_launch(void* const* d_in, const int* in_sizes, int n_in,
                              void* d_out, int out_size)
{
    const float* node = (const float*)d_in[0];
    const int*   nbr  = (const int*)  d_in[1];
    const float* ef   = (const float*)d_in[2];
    const float* Wq   = (const float*)d_in[3];
    const float* bq   = (const float*)d_in[4];
    const float* Wk   = (const float*)d_in[5];
    const float* bk   = (const float*)d_in[6];
    const float* Wv   = (const float*)d_in[7];
    const float* bv   = (const float*)d_in[8];
    const float* We   = (const float*)d_in[9];
    const float* be   = (const float*)d_in[10];
    const float* Wo   = (const float*)d_in[11];
    const float* bo   = (const float*)d_in[12];
    const float* ln1g = (const float*)d_in[13];
    const float* ln1b = (const float*)d_in[14];
    const float* ln2g = (const float*)d_in[15];
    const float* ln2b = (const float*)d_in[16];
    const float* Wf1  = (const float*)d_in[17];
    const float* bf1  = (const float*)d_in[18];
    const float* Wf2  = (const float*)d_in[19];
    const float* bf2  = (const float*)d_in[20];
    float* out = (float*)d_out;

    static float *Qd = nullptr, *Kd, *Vd, *eattd, *attnd, *x1d, *fd, *partd;
    if (!Qd) {
        cudaGetSymbolAddress((void**)&Qd,    g_Q);
        cudaGetSymbolAddress((void**)&Kd,    g_K);
        cudaGetSymbolAddress((void**)&Vd,    g_V);
        cudaGetSymbolAddress((void**)&eattd, g_eatt);
        cudaGetSymbolAddress((void**)&attnd, g_attn);
        cudaGetSymbolAddress((void**)&x1d,   g_x1);
        cudaGetSymbolAddress((void**)&fd,    g_f);
        cudaGetSymbolAddress((void**)&partd, g_part);
    }
    Parts4 parts;
    for (int i = 0; i < 4; i++) parts.p[i] = partd + (size_t)i * NN * HID;

    // Fused QKV projections
    QKVArgs qa;
    qa.W[0] = Wq; qa.W[1] = Wk; qa.W[2] = Wv;
    qa.b[0] = bq; qa.b[1] = bk; qa.b[2] = bv;
    qa.O[0] = Qd; qa.O[1] = Kd; qa.O[2] = Vd;
    qkv_gemm_kernel<<<dim3(12, NN/GBM), 128>>>(node, qa, HID, HID);

    // Edge bias
    edge_kernel<<<(EE + 255)/256, 256>>>(ef, We, be, eattd);

    // Sparse attention
    attn_kernel<<<NN, HH*32>>>(Qd, Kd, Vd, nbr, eattd, attnd);

    // Output projection (split-K 2) + fused reduce+bias+residual+LN1
    gemm_split_kernel<<<dim3(HID/GBN, NN/GBM, 2), 128>>>(attnd, Wo, parts, HID, HID, HID/2);
    add_ln_multi<2><<<NN, HID>>>(parts, bo, node, ln1g, ln1b, x1d);

    // FFN1
    gemm_kernel<true><<<dim3(FFN/GBN, NN/GBM), 128>>>(x1d, Wf1, bf1, fd, FFN, HID);

    // FFN2 (split-K 4) + fused reduce+bias+residual+LN2
    gemm_split_kernel<<<dim3(HID/GBN, NN/GBM, 4), 128>>>(fd, Wf2, parts, HID, FFN, FFN/4);
    add_ln_multi<4><<<NN, HID>>>(parts, bf2, x1d, ln2g, ln2b, out);
}